// round 1
// baseline (speedup 1.0000x reference)
#include <cuda_runtime.h>
#include <cuda_fp16.h>
#include <cstdint>

#define NROW 12288
#define INF  128
#define OUTF 64
#define LOG2E 1.44269504088896341f
#define KSPLIT 2
#define AS_STRIDE 136   // halfs per row (128 + 8 pad -> 68 words, conflict-free)
#define BS_STRIDE 136

// ---------------- device scratch (no allocations allowed) ----------------
__device__ float  g_wh1[NROW];
__device__ float  g_wh2[NROW];
__device__ float  g_wh2max;
__device__ __half g_hT[OUTF * NROW];          // h transposed, fp16: [f][j]
__device__ float  g_S[KSPLIT][NROW * 72];     // partial (E' @ [h|1|0]) per K-split

// ---------------- Kernel A: h = input @ W, wh1/wh2, hT fp16 ----------------
__global__ void kA(const float* __restrict__ inp, const float* __restrict__ W,
                   const float* __restrict__ a) {
    __shared__ float in_s[4][INF];
    __shared__ float red1[8], red2[8];
    int tid = threadIdx.x;
    int i0 = blockIdx.x * 4;
    for (int e = tid; e < 4 * INF; e += 256)
        in_s[e >> 7][e & 127] = inp[(i0 + (e >> 7)) * INF + (e & 127)];
    __syncthreads();
    int f = tid & 63, r = tid >> 6;
    float acc = 0.f;
#pragma unroll 8
    for (int k = 0; k < INF; k++)
        acc = fmaf(in_s[r][k], W[k * OUTF + f], acc);
    int i = i0 + r;
    g_hT[f * NROW + i] = __float2half(acc);
    float p1 = acc * a[f];
    float p2 = acc * a[64 + f];
#pragma unroll
    for (int o = 16; o > 0; o >>= 1) {
        p1 += __shfl_xor_sync(~0u, p1, o);
        p2 += __shfl_xor_sync(~0u, p2, o);
    }
    int w = tid >> 5;
    if ((tid & 31) == 0) { red1[w] = p1; red2[w] = p2; }
    __syncthreads();
    if (tid < 4) {
        g_wh1[i0 + tid] = red1[2 * tid] + red1[2 * tid + 1];
        g_wh2[i0 + tid] = red2[2 * tid] + red2[2 * tid + 1];
    }
}

// ---------------- Kernel A2: global max of wh2 ----------------
__global__ void kMax() {
    __shared__ float red[8];
    int tid = threadIdx.x;
    float m = -1e30f;
    for (int i = tid; i < NROW; i += 256) m = fmaxf(m, g_wh2[i]);
#pragma unroll
    for (int o = 16; o > 0; o >>= 1) m = fmaxf(m, __shfl_xor_sync(~0u, m, o));
    if ((tid & 31) == 0) red[tid >> 5] = m;
    __syncthreads();
    if (tid == 0) {
        float mm = red[0];
#pragma unroll
        for (int w = 1; w < 8; w++) mm = fmaxf(mm, red[w]);
        g_wh2max = mm;
    }
}

// ---------------- Kernel B: fused mask + lrelu + exp + (E' @ [h|1]) ----------------
// grid (96, KSPLIT), 256 threads. Tile: 128 rows(i) x 128 cols(j), N=72 output cols.
__global__ void __launch_bounds__(256, 2) kMain(const int* __restrict__ adj) {
    extern __shared__ char smem_raw[];
    __half* A_s = (__half*)smem_raw;                                     // 128 x 136
    __half* B_s = (__half*)(smem_raw + 128 * AS_STRIDE * 2);             // 72 x 136
    float*  wh1_s = (float*)(smem_raw + 128 * AS_STRIDE * 2 + 72 * BS_STRIDE * 2);
    float*  m2_s  = wh1_s + 128;

    int tid  = threadIdx.x;
    int lane = tid & 31, w = tid >> 5;
    int i0 = blockIdx.x * 128;
    int split = blockIdx.y;
    int jbase = split * (NROW / KSPLIT);

    uint32_t* B_su = (uint32_t*)B_s;
    // ones column (n=64) and zero pad rows (n=65..71), written once
    for (int e = tid; e < 8 * 68; e += 256) {
        int rr = e / 68, c = e % 68;
        B_su[(64 + rr) * 68 + c] = (rr == 0) ? 0x3C003C00u : 0u;
    }
    if (tid < 128) {
        float w1 = g_wh1[i0 + tid];
        float s = w1 + g_wh2max;
        float m = fmaxf(s, 0.2f * s);       // lrelu upper bound of row max
        wh1_s[tid] = w1;
        m2_s[tid]  = m * LOG2E;
    }

    float acc[9][4];
#pragma unroll
    for (int nt = 0; nt < 9; nt++)
#pragma unroll
        for (int q = 0; q < 4; q++) acc[nt][q] = 0.f;

    uint32_t A_base = (uint32_t)__cvta_generic_to_shared(A_s);
    uint32_t B_base = (uint32_t)__cvta_generic_to_shared(B_s);
    uint32_t a_ptr_row = A_base + (uint32_t)(((w * 16 + (lane & 15)) * AS_STRIDE + ((lane >> 4) * 8)) * 2);
    int l15 = lane & 15;
    uint32_t b_ptr_row = B_base + (uint32_t)((((l15 & 7) * BS_STRIDE) + ((l15 >> 3) * 8)) * 2);

    const uint32_t* hTu = (const uint32_t*)g_hT;
    const int ntiles = (NROW / KSPLIT) / 128;   // 48

    for (int jt = 0; jt < ntiles; jt++) {
        int j0 = jbase + jt * 128;
        __syncthreads();   // previous MMA done before overwriting tiles

        // build B_s rows 0..63 from hT (fp16), coalesced
        {
            int j0h = j0 >> 1;
            for (int e = tid; e < 64 * 64; e += 256) {
                int n = e >> 6, kp = e & 63;
                B_su[n * 68 + kp] = hTu[n * (NROW / 2) + j0h + kp];
            }
        }
        // build A_s (E' tile): warp w handles rows w*16..w*16+15, lane covers 4 j's
        {
            float4 wv = *(const float4*)(g_wh2 + j0 + lane * 4);
#pragma unroll 4
            for (int rr = 0; rr < 16; rr++) {
                int row = w * 16 + rr;
                const int4 av = *(const int4*)(adj + (long long)(i0 + row) * NROW + j0 + lane * 4);
                float w1 = wh1_s[row];
                float m2 = m2_s[row];
                float s0 = w1 + wv.x, s1 = w1 + wv.y, s2 = w1 + wv.z, s3 = w1 + wv.w;
                s0 = fmaxf(s0, 0.2f * s0); s1 = fmaxf(s1, 0.2f * s1);
                s2 = fmaxf(s2, 0.2f * s2); s3 = fmaxf(s3, 0.2f * s3);
                float x0 = fmaf(s0, LOG2E, -m2), x1 = fmaf(s1, LOG2E, -m2);
                float x2 = fmaf(s2, LOG2E, -m2), x3 = fmaf(s3, LOG2E, -m2);
                float e0, e1, e2, e3;
                asm("ex2.approx.f32 %0, %1;" : "=f"(e0) : "f"(x0));
                asm("ex2.approx.f32 %0, %1;" : "=f"(e1) : "f"(x1));
                asm("ex2.approx.f32 %0, %1;" : "=f"(e2) : "f"(x2));
                asm("ex2.approx.f32 %0, %1;" : "=f"(e3) : "f"(x3));
                e0 = av.x ? e0 : 0.f; e1 = av.y ? e1 : 0.f;
                e2 = av.z ? e2 : 0.f; e3 = av.w ? e3 : 0.f;
                __half2 h01 = __floats2half2_rn(e0, e1);
                __half2 h23 = __floats2half2_rn(e2, e3);
                uint2 pk;
                pk.x = reinterpret_cast<uint32_t&>(h01);
                pk.y = reinterpret_cast<uint32_t&>(h23);
                *(uint2*)(A_s + row * AS_STRIDE + lane * 4) = pk;
            }
        }
        __syncthreads();

        // MMA: warp w owns m-tile rows w*16..+15, all 9 n-tiles
#pragma unroll
        for (int ks = 0; ks < 8; ks++) {
            uint32_t a0, a1, a2, a3;
            uint32_t aaddr = a_ptr_row + (uint32_t)(ks * 16 * 2);
            asm volatile("ldmatrix.sync.aligned.m8n8.x4.shared.b16 {%0,%1,%2,%3}, [%4];"
                         : "=r"(a0), "=r"(a1), "=r"(a2), "=r"(a3) : "r"(aaddr));
#pragma unroll
            for (int nt = 0; nt < 9; nt++) {
                uint32_t b0, b1;
                uint32_t baddr = b_ptr_row + (uint32_t)(((nt * 8) * BS_STRIDE + ks * 16) * 2);
                asm volatile("ldmatrix.sync.aligned.m8n8.x2.shared.b16 {%0,%1}, [%2];"
                             : "=r"(b0), "=r"(b1) : "r"(baddr));
                asm volatile("mma.sync.aligned.m16n8k16.row.col.f32.f16.f16.f32 "
                             "{%0,%1,%2,%3}, {%4,%5,%6,%7}, {%8,%9}, {%0,%1,%2,%3};"
                             : "+f"(acc[nt][0]), "+f"(acc[nt][1]), "+f"(acc[nt][2]), "+f"(acc[nt][3])
                             : "r"(a0), "r"(a1), "r"(a2), "r"(a3), "r"(b0), "r"(b1));
            }
        }
    }

    // write out partial S
    int g = lane >> 2, t = lane & 3;
    float* Sp = g_S[split];
#pragma unroll
    for (int nt = 0; nt < 9; nt++) {
        int col = nt * 8 + t * 2;
        int row0 = i0 + w * 16 + g;
        *(float2*)(Sp + row0 * 72 + col)       = make_float2(acc[nt][0], acc[nt][1]);
        *(float2*)(Sp + (row0 + 8) * 72 + col) = make_float2(acc[nt][2], acc[nt][3]);
    }
}

// ---------------- Kernel C: normalize + ELU ----------------
__global__ void kEpi(float* __restrict__ out) {
    int idx = blockIdx.x * 256 + threadIdx.x;   // NROW*64 total
    int i = idx >> 6, f = idx & 63;
    float l = g_S[0][i * 72 + 64] + g_S[1][i * 72 + 64];
    float v = (g_S[0][i * 72 + f] + g_S[1][i * 72 + f]) / l;
    out[idx] = v > 0.f ? v : expm1f(v);
}

// ---------------- launch ----------------
extern "C" void kernel_launch(void* const* d_in, const int* in_sizes, int n_in,
                              void* d_out, int out_size) {
    (void)in_sizes; (void)n_in; (void)out_size;
    const float* inp = (const float*)d_in[0];
    const int*   adj = (const int*)d_in[1];
    const float* W   = (const float*)d_in[2];
    const float* a   = (const float*)d_in[3];

    const int smem_bytes = 128 * AS_STRIDE * 2 + 72 * BS_STRIDE * 2 + 256 * 4; // 55424
    cudaFuncSetAttribute(kMain, cudaFuncAttributeMaxDynamicSharedMemorySize, smem_bytes);

    kA<<<NROW / 4, 256>>>(inp, W, a);
    kMax<<<1, 256>>>();
    kMain<<<dim3(NROW / 128, KSPLIT), 256, smem_bytes>>>(adj);
    kEpi<<<NROW * OUTF / 256, 256>>>((float*)d_out);
}